// round 7
// baseline (speedup 1.0000x reference)
#include <cuda_runtime.h>

#define MPTS 100000
#define KN   27

// Scratch (__device__ globals)
__device__ float g_Qp[MPTS * 64];
__device__ float g_Kb[MPTS * 64];
__device__ float g_Vo[MPTS * 64];
__device__ float g_Wvo[96 * 64];

// ---------------------------------------------------------------------------
// Kernel W: fold W_vo = Wv(96x64) @ Wo(64x64)  -> [96,64]
// ---------------------------------------------------------------------------
__global__ void kW(const float* __restrict__ Wv, const float* __restrict__ Wo)
{
    int t = blockIdx.x * 256 + threadIdx.x;
    if (t < 96 * 64) {
        int row = t >> 6, col = t & 63;
        float s = 0.f;
#pragma unroll 16
        for (int i = 0; i < 64; i++)
            s = fmaf(Wv[row * 64 + i], Wo[i * 64 + col], s);
        g_Wvo[t] = s;
    }
}

// ---------------------------------------------------------------------------
// Kernel A1: 4 points/warp.  a = geo@Wg -> LN -> relu -> q
//            bdy = q@Wb+bb ; Qp = q@Wq ; Kb = q@Wk
// ---------------------------------------------------------------------------
__global__ void __launch_bounds__(256) kA1(
    const float* __restrict__ geo, const float* __restrict__ Wg,
    const float* __restrict__ gam, const float* __restrict__ bet,
    const float* __restrict__ Wb, const float* __restrict__ bb,
    const float* __restrict__ Wq, const float* __restrict__ Wk,
    float* __restrict__ out)
{
    extern __shared__ float sm[];
    float* sWg = sm;            // 4096
    float* sWq = sm + 4096;     // 4096
    float* sWk = sm + 8192;     // 4096
    float* sGm = sm + 12288;    // 64
    float* sBt = sm + 12352;    // 64
    float* sWb = sm + 12416;    // 64
    float* stage = sm + 12480;  // 8 warps * 256

    for (int i = threadIdx.x; i < 4096; i += 256) {
        sWg[i] = Wg[i]; sWq[i] = Wq[i]; sWk[i] = Wk[i];
    }
    if (threadIdx.x < 64) {
        sGm[threadIdx.x] = gam[threadIdx.x];
        sBt[threadIdx.x] = bet[threadIdx.x];
        sWb[threadIdx.x] = Wb[threadIdx.x];
    }
    __syncthreads();

    const int lane = threadIdx.x & 31;
    float* myS = stage + (threadIdx.x >> 5) * 256;
    const int warp = (blockIdx.x * blockDim.x + threadIdx.x) >> 5;
    const int nw   = (gridDim.x * blockDim.x) >> 5;
    const float bb0 = bb[0];
    const float2 gm = *(const float2*)&sGm[2 * lane];
    const float2 bt = *(const float2*)&sBt[2 * lane];
    const float2 wb = *(const float2*)&sWb[2 * lane];

    for (int p4 = warp * 4; p4 < MPTS; p4 += nw * 4) {
        {
            const float4* gsrc = (const float4*)(geo + (size_t)p4 * 64);
            float4* sdst = (float4*)myS;
            sdst[lane]      = gsrc[lane];
            sdst[lane + 32] = gsrc[lane + 32];
        }
        __syncwarp();

        float a0[4] = {0,0,0,0}, a1[4] = {0,0,0,0};
#pragma unroll
        for (int i = 0; i < 64; i += 4) {
            float xj[4][4];
#pragma unroll
            for (int j = 0; j < 4; j++) {
                float4 t = *(const float4*)&myS[j * 64 + i];
                xj[j][0] = t.x; xj[j][1] = t.y; xj[j][2] = t.z; xj[j][3] = t.w;
            }
#pragma unroll
            for (int s = 0; s < 4; s++) {
                float2 w = *(const float2*)&sWg[(i + s) * 64 + 2 * lane];
#pragma unroll
                for (int j = 0; j < 4; j++) {
                    a0[j] = fmaf(xj[j][s], w.x, a0[j]);
                    a1[j] = fmaf(xj[j][s], w.y, a1[j]);
                }
            }
        }
        __syncwarp();

        float t[4];
#pragma unroll
        for (int j = 0; j < 4; j++) t[j] = a0[j] + a1[j];
#pragma unroll
        for (int o = 16; o; o >>= 1)
#pragma unroll
            for (int j = 0; j < 4; j++) t[j] += __shfl_xor_sync(~0u, t[j], o);
        float q0[4], q1[4], vr[4];
#pragma unroll
        for (int j = 0; j < 4; j++) {
            float mu = t[j] * (1.f / 64.f);
            a0[j] -= mu; a1[j] -= mu;
            vr[j] = a0[j] * a0[j] + a1[j] * a1[j];
        }
#pragma unroll
        for (int o = 16; o; o >>= 1)
#pragma unroll
            for (int j = 0; j < 4; j++) vr[j] += __shfl_xor_sync(~0u, vr[j], o);
#pragma unroll
        for (int j = 0; j < 4; j++) {
            float rs = rsqrtf(vr[j] * (1.f / 64.f) + 1e-5f);
            q0[j] = fmaxf(fmaf(a0[j] * rs, gm.x, bt.x), 0.f);
            q1[j] = fmaxf(fmaf(a1[j] * rs, gm.y, bt.y), 0.f);
        }

        float bd[4];
#pragma unroll
        for (int j = 0; j < 4; j++) bd[j] = q0[j] * wb.x + q1[j] * wb.y;
#pragma unroll
        for (int o = 16; o; o >>= 1)
#pragma unroll
            for (int j = 0; j < 4; j++) bd[j] += __shfl_xor_sync(~0u, bd[j], o);
        if (lane == 0) {
#pragma unroll
            for (int j = 0; j < 4; j++)
                out[(size_t)13 * MPTS + p4 + j] = bd[j] + bb0;
        }

#pragma unroll
        for (int j = 0; j < 4; j++)
            *(float2*)&myS[j * 64 + 2 * lane] = make_float2(q0[j], q1[j]);
        __syncwarp();

        float u0[4] = {0,0,0,0}, u1[4] = {0,0,0,0};
        float v0[4] = {0,0,0,0}, v1[4] = {0,0,0,0};
#pragma unroll
        for (int i = 0; i < 64; i += 4) {
            float xj[4][4];
#pragma unroll
            for (int j = 0; j < 4; j++) {
                float4 tt = *(const float4*)&myS[j * 64 + i];
                xj[j][0] = tt.x; xj[j][1] = tt.y; xj[j][2] = tt.z; xj[j][3] = tt.w;
            }
#pragma unroll
            for (int s = 0; s < 4; s++) {
                float2 wq = *(const float2*)&sWq[(i + s) * 64 + 2 * lane];
                float2 wk = *(const float2*)&sWk[(i + s) * 64 + 2 * lane];
#pragma unroll
                for (int j = 0; j < 4; j++) {
                    u0[j] = fmaf(xj[j][s], wq.x, u0[j]);
                    u1[j] = fmaf(xj[j][s], wq.y, u1[j]);
                    v0[j] = fmaf(xj[j][s], wk.x, v0[j]);
                    v1[j] = fmaf(xj[j][s], wk.y, v1[j]);
                }
            }
        }
        __syncwarp();
#pragma unroll
        for (int j = 0; j < 4; j++) {
            size_t o = (size_t)(p4 + j) * 64 + 2 * lane;
            *(float2*)&g_Qp[o] = make_float2(u0[j], u1[j]);
            *(float2*)&g_Kb[o] = make_float2(v0[j], v1[j]);
        }
    }
}

// ---------------------------------------------------------------------------
// Kernel A2: 4 points/warp.  Vo = sem @ W_vo   (96 -> 64, single GEMV)
// ---------------------------------------------------------------------------
__global__ void __launch_bounds__(256) kA2(const float* __restrict__ sem)
{
    extern __shared__ float sm[];
    float* sW = sm;             // 6144
    float* stage = sm + 6144;   // 8 warps * 384

    for (int i = threadIdx.x; i < 6144; i += 256) sW[i] = g_Wvo[i];
    __syncthreads();

    const int lane = threadIdx.x & 31;
    float* myS = stage + (threadIdx.x >> 5) * 384;
    const int warp = (blockIdx.x * blockDim.x + threadIdx.x) >> 5;
    const int nw   = (gridDim.x * blockDim.x) >> 5;

    for (int p4 = warp * 4; p4 < MPTS; p4 += nw * 4) {
        {
            const float4* ssrc = (const float4*)(sem + (size_t)p4 * 96);
            float4* sdst = (float4*)myS;
            sdst[lane]      = ssrc[lane];
            sdst[lane + 32] = ssrc[lane + 32];
            sdst[lane + 64] = ssrc[lane + 64];
        }
        __syncwarp();

        float o0[4] = {0,0,0,0}, o1[4] = {0,0,0,0};
#pragma unroll
        for (int i = 0; i < 96; i += 4) {
            float xj[4][4];
#pragma unroll
            for (int j = 0; j < 4; j++) {
                float4 t = *(const float4*)&myS[j * 96 + i];
                xj[j][0] = t.x; xj[j][1] = t.y; xj[j][2] = t.z; xj[j][3] = t.w;
            }
#pragma unroll
            for (int s = 0; s < 4; s++) {
                float2 w = *(const float2*)&sW[(i + s) * 64 + 2 * lane];
#pragma unroll
                for (int j = 0; j < 4; j++) {
                    o0[j] = fmaf(xj[j][s], w.x, o0[j]);
                    o1[j] = fmaf(xj[j][s], w.y, o1[j]);
                }
            }
        }
        __syncwarp();
#pragma unroll
        for (int j = 0; j < 4; j++)
            *(float2*)&g_Vo[(size_t)(p4 + j) * 64 + 2 * lane] = make_float2(o0[j], o1[j]);
    }
}

// ---------------------------------------------------------------------------
// Kernel B: attention, 1 point/warp.
// Logits: 4-lane-group cooperative dot. lane = g*4+s; pass t handles
// neighbor k = t*8+g; lane s dots columns [16s,16s+16) with LDG.128
// (coalesced 256B/group), 2-level xor reduce, STS of 1 float.
// Aggregation: (aff,idx) pairs broadcast from smem (1 LDS.64/k).
// ---------------------------------------------------------------------------
__global__ void __launch_bounds__(256, 4) kB(
    const int* __restrict__ coords, const int* __restrict__ nbr,
    const float* __restrict__ pe, const float* __restrict__ bo,
    float* __restrict__ out)
{
    __shared__ float sPe[KN * 64];
    __shared__ float sBo[64];
    __shared__ float sQ[8][64];
    __shared__ float sAI[8][64];
    __shared__ float sL[8][32];

    for (int i = threadIdx.x; i < KN * 64; i += 256) sPe[i] = pe[i];
    if (threadIdx.x < 64) sBo[threadIdx.x] = bo[threadIdx.x];
    __syncthreads();

    const int lane = threadIdx.x & 31;
    const int wid  = threadIdx.x >> 5;
    const int g = lane >> 2, s = lane & 3;
    const int warp = (blockIdx.x * blockDim.x + threadIdx.x) >> 5;
    const int nw   = (gridDim.x * blockDim.x) >> 5;
    const float2 bo2 = *(const float2*)&sBo[2 * lane];

    const size_t off_aff = (size_t)14 * MPTS;
    const size_t off_ref = (size_t)41 * MPTS;
    const size_t off_nbr = (size_t)105 * MPTS;
    const size_t off_msk = (size_t)132 * MPTS;

    for (int p = warp; p < MPTS; p += nw) {
        // stage q row into per-warp smem
        {
            float2 q2 = *(const float2*)&g_Qp[(size_t)p * 64 + 2 * lane];
            *(float2*)&sQ[wid][2 * lane] = q2;
        }

        int cx = coords[3 * p], cy = coords[3 * p + 1], cz = coords[3 * p + 2];

        // packed = idx | pos<<17 | valid<<22
        int packed = 0;
        if (lane < KN) {
            int idx = nbr[(size_t)p * KN + lane];
            int rx = coords[3 * idx] - cx, ry = coords[3 * idx + 1] - cy,
                rz = coords[3 * idx + 2] - cz;
            int vld = (max(abs(rx), max(abs(ry), abs(rz))) <= 1);
            int pos = min(max(rx + 1, 0), 2) * 9 + min(max(ry + 1, 0), 2) * 3
                    + min(max(rz + 1, 0), 2);
            packed = idx | (pos << 17) | (vld << 22);
        }
        __syncwarp();

        // phase 1: group-cooperative logits (passes t=0..3, k=t*8+g)
#pragma unroll
        for (int t = 0; t < 4; t++) {
            int k = t * 8 + g;
            int pk = __shfl_sync(~0u, packed, k);
            int idx = pk & 0x1FFFF;
            int pos = (pk >> 17) & 31;
            const float4* kb = (const float4*)&g_Kb[(size_t)idx * 64 + s * 16];
            const float4* pr = (const float4*)&sPe[pos * 64 + s * 16];
            const float4* qq = (const float4*)&sQ[wid][s * 16];
            float acc = 0.f;
#pragma unroll
            for (int c = 0; c < 4; c++) {
                float4 kv = kb[c];
                float4 pv = pr[c];
                float4 qv = qq[c];
                acc = fmaf(qv.x, kv.x + pv.x, acc);
                acc = fmaf(qv.y, kv.y + pv.y, acc);
                acc = fmaf(qv.z, kv.z + pv.z, acc);
                acc = fmaf(qv.w, kv.w + pv.w, acc);
            }
            acc += __shfl_xor_sync(~0u, acc, 1);
            acc += __shfl_xor_sync(~0u, acc, 2);
            if (s == 0 && k < 28) sL[wid][k] = acc;
        }
        __syncwarp();

        // logit for this lane's neighbor
        float logit = -1e30f;
        if (lane < KN)
            logit = (packed >> 22) ? sL[wid][lane] * 0.125f : -10000.0f;

        // softmax over warp
        float mx = logit;
#pragma unroll
        for (int o = 16; o; o >>= 1)
            mx = fmaxf(mx, __shfl_xor_sync(~0u, mx, o));
        float e = __expf(logit - mx);
        float ssum = e;
#pragma unroll
        for (int o = 16; o; o >>= 1)
            ssum += __shfl_xor_sync(~0u, ssum, o);
        float aff = e / ssum;

        // publish (aff, packed) pairs for broadcast loads
        if (lane < KN)
            *(float2*)&sAI[wid][2 * lane] =
                make_float2(aff, __int_as_float(packed));
        __syncwarp();

        // aggregate Vo (broadcast LDS pair + gather; 2 accumulators)
        float2 r = *(const float2*)&g_Vo[(size_t)p * 64 + 2 * lane];
        float2 r2 = make_float2(0.f, 0.f);
#pragma unroll
        for (int k = 0; k < KN; k += 2) {
            float2 ai = *(const float2*)&sAI[wid][2 * k];
            int ia = __float_as_int(ai.y) & 0x1FFFF;
            float2 v = *(const float2*)&g_Vo[(size_t)ia * 64 + 2 * lane];
            r.x = fmaf(ai.x, v.x, r.x); r.y = fmaf(ai.x, v.y, r.y);
            if (k + 1 < KN) {
                float2 bi = *(const float2*)&sAI[wid][2 * k + 2];
                int ib = __float_as_int(bi.y) & 0x1FFFF;
                float2 w = *(const float2*)&g_Vo[(size_t)ib * 64 + 2 * lane];
                r2.x = fmaf(bi.x, w.x, r2.x); r2.y = fmaf(bi.x, w.y, r2.y);
            }
        }
        r.x += r2.x; r.y += r2.y;

        *(float2*)&out[off_ref + (size_t)p * 64 + 2 * lane] =
            make_float2(r.x + bo2.x, r.y + bo2.y);
        if (lane < KN) {
            size_t a = (size_t)p * KN + lane;
            out[off_aff + a] = aff;
            out[off_nbr + a] = (float)(packed & 0x1FFFF);
            out[off_msk + a] = (packed >> 22) ? 1.f : 0.f;
        }
        __syncwarp();
    }
}

// ---------------------------------------------------------------------------
// Kernel C: logits = refined_feat @ Wc + bc  (reads refined from out buffer)
// ---------------------------------------------------------------------------
__global__ void __launch_bounds__(256) kC(
    const float* __restrict__ Wc, const float* __restrict__ bc,
    float* __restrict__ out)
{
    __shared__ float sWc[832];
    __shared__ float sBc[16];
    __shared__ float stage[8 * 256];
    for (int i = threadIdx.x; i < 832; i += 256) sWc[i] = Wc[i];
    if (threadIdx.x < 16) sBc[threadIdx.x] = (threadIdx.x < 13) ? bc[threadIdx.x] : 0.f;
    __syncthreads();

    const int lane = threadIdx.x & 31;
    float* myS = stage + (threadIdx.x >> 5) * 256;
    const int warp = (blockIdx.x * blockDim.x + threadIdx.x) >> 5;
    const int nw   = (gridDim.x * blockDim.x) >> 5;
    const float* refv = out + (size_t)41 * MPTS;

    for (int p4 = warp * 4; p4 < MPTS; p4 += nw * 4) {
        {
            const float4* rs = (const float4*)(refv + (size_t)p4 * 64);
            float4* sdst = (float4*)myS;
            sdst[lane]      = rs[lane];
            sdst[lane + 32] = rs[lane + 32];
        }
        __syncwarp();

        float c[4];
#pragma unroll
        for (int j = 0; j < 4; j++) c[j] = (lane < 13) ? sBc[lane] : 0.f;
#pragma unroll
        for (int i = 0; i < 64; i += 4) {
            float xj[4][4];
#pragma unroll
            for (int j = 0; j < 4; j++) {
                float4 t = *(const float4*)&myS[j * 64 + i];
                xj[j][0] = t.x; xj[j][1] = t.y; xj[j][2] = t.z; xj[j][3] = t.w;
            }
#pragma unroll
            for (int s = 0; s < 4; s++) {
                float w = (lane < 13) ? sWc[(i + s) * 13 + lane] : 0.f;
#pragma unroll
                for (int j = 0; j < 4; j++) c[j] = fmaf(xj[j][s], w, c[j]);
            }
        }
        __syncwarp();
        if (lane < 13) {
#pragma unroll
            for (int j = 0; j < 4; j++)
                out[(size_t)(p4 + j) * 13 + lane] = c[j];
        }
    }
}

extern "C" void kernel_launch(void* const* d_in, const int* in_sizes, int n_in,
                              void* d_out, int out_size)
{
    const float* geo    = (const float*)d_in[0];
    const float* sem    = (const float*)d_in[1];
    const int*   coords = (const int*)d_in[2];
    const int*   nbr    = (const int*)d_in[3];   // int32 (JAX x64 off)
    const float* Wg     = (const float*)d_in[4];
    const float* gam    = (const float*)d_in[5];
    const float* bet    = (const float*)d_in[6];
    const float* Wb     = (const float*)d_in[7];
    const float* bb     = (const float*)d_in[8];
    const float* Wq     = (const float*)d_in[9];
    const float* Wk     = (const float*)d_in[10];
    const float* Wv     = (const float*)d_in[11];
    const float* pe     = (const float*)d_in[12];
    const float* Wo     = (const float*)d_in[13];
    const float* bo     = (const float*)d_in[14];
    const float* Wc     = (const float*)d_in[15];
    const float* bc     = (const float*)d_in[16];
    float* out = (float*)d_out;

    const int smemA1 = 14528 * 4;   // 58112 B
    const int smemA2 = 9216 * 4;    // 36864 B
    cudaFuncSetAttribute(kA1, cudaFuncAttributeMaxDynamicSharedMemorySize, smemA1);

    kW<<<24, 256>>>(Wv, Wo);
    kA1<<<592, 256, smemA1>>>(geo, Wg, gam, bet, Wb, bb, Wq, Wk, out);
    kA2<<<592, 256, smemA2>>>(sem);
    kB<<<12500, 256>>>(coords, nbr, pe, bo, out);
    kC<<<592, 256>>>(Wc, bc, out);
}

// round 8
// speedup vs baseline: 1.3861x; 1.3861x over previous
#include <cuda_runtime.h>

#define MPTS 100000
#define KN   27

// Scratch (__device__ globals)
__device__ float g_Qp[MPTS * 64];
__device__ float g_Kb[MPTS * 64];
__device__ float g_Vo[MPTS * 64];
__device__ float g_Wvo[96 * 64];

// ---------------------------------------------------------------------------
// Kernel W: fold W_vo = Wv(96x64) @ Wo(64x64)  -> [96,64]
// ---------------------------------------------------------------------------
__global__ void kW(const float* __restrict__ Wv, const float* __restrict__ Wo)
{
    int t = blockIdx.x * 256 + threadIdx.x;
    if (t < 96 * 64) {
        int row = t >> 6, col = t & 63;
        float s = 0.f;
#pragma unroll 16
        for (int i = 0; i < 64; i++)
            s = fmaf(Wv[row * 64 + i], Wo[i * 64 + col], s);
        g_Wvo[t] = s;
    }
}

// ---------------------------------------------------------------------------
// Kernel A1: 4 points/warp.  a = geo@Wg -> LN -> relu -> q
//            bdy = q@Wb+bb ; Qp = q@Wq ; Kb = q@Wk
// ---------------------------------------------------------------------------
__global__ void __launch_bounds__(256) kA1(
    const float* __restrict__ geo, const float* __restrict__ Wg,
    const float* __restrict__ gam, const float* __restrict__ bet,
    const float* __restrict__ Wb, const float* __restrict__ bb,
    const float* __restrict__ Wq, const float* __restrict__ Wk,
    float* __restrict__ out)
{
    extern __shared__ float sm[];
    float* sWg = sm;            // 4096
    float* sWq = sm + 4096;     // 4096
    float* sWk = sm + 8192;     // 4096
    float* sGm = sm + 12288;    // 64
    float* sBt = sm + 12352;    // 64
    float* sWb = sm + 12416;    // 64
    float* stage = sm + 12480;  // 8 warps * 256

    for (int i = threadIdx.x; i < 4096; i += 256) {
        sWg[i] = Wg[i]; sWq[i] = Wq[i]; sWk[i] = Wk[i];
    }
    if (threadIdx.x < 64) {
        sGm[threadIdx.x] = gam[threadIdx.x];
        sBt[threadIdx.x] = bet[threadIdx.x];
        sWb[threadIdx.x] = Wb[threadIdx.x];
    }
    __syncthreads();

    const int lane = threadIdx.x & 31;
    float* myS = stage + (threadIdx.x >> 5) * 256;
    const int warp = (blockIdx.x * blockDim.x + threadIdx.x) >> 5;
    const int nw   = (gridDim.x * blockDim.x) >> 5;
    const float bb0 = bb[0];
    const float2 gm = *(const float2*)&sGm[2 * lane];
    const float2 bt = *(const float2*)&sBt[2 * lane];
    const float2 wb = *(const float2*)&sWb[2 * lane];

    for (int p4 = warp * 4; p4 < MPTS; p4 += nw * 4) {
        {
            const float4* gsrc = (const float4*)(geo + (size_t)p4 * 64);
            float4* sdst = (float4*)myS;
            sdst[lane]      = gsrc[lane];
            sdst[lane + 32] = gsrc[lane + 32];
        }
        __syncwarp();

        float a0[4] = {0,0,0,0}, a1[4] = {0,0,0,0};
#pragma unroll
        for (int i = 0; i < 64; i += 4) {
            float xj[4][4];
#pragma unroll
            for (int j = 0; j < 4; j++) {
                float4 t = *(const float4*)&myS[j * 64 + i];
                xj[j][0] = t.x; xj[j][1] = t.y; xj[j][2] = t.z; xj[j][3] = t.w;
            }
#pragma unroll
            for (int s = 0; s < 4; s++) {
                float2 w = *(const float2*)&sWg[(i + s) * 64 + 2 * lane];
#pragma unroll
                for (int j = 0; j < 4; j++) {
                    a0[j] = fmaf(xj[j][s], w.x, a0[j]);
                    a1[j] = fmaf(xj[j][s], w.y, a1[j]);
                }
            }
        }
        __syncwarp();

        float t[4];
#pragma unroll
        for (int j = 0; j < 4; j++) t[j] = a0[j] + a1[j];
#pragma unroll
        for (int o = 16; o; o >>= 1)
#pragma unroll
            for (int j = 0; j < 4; j++) t[j] += __shfl_xor_sync(~0u, t[j], o);
        float q0[4], q1[4], vr[4];
#pragma unroll
        for (int j = 0; j < 4; j++) {
            float mu = t[j] * (1.f / 64.f);
            a0[j] -= mu; a1[j] -= mu;
            vr[j] = a0[j] * a0[j] + a1[j] * a1[j];
        }
#pragma unroll
        for (int o = 16; o; o >>= 1)
#pragma unroll
            for (int j = 0; j < 4; j++) vr[j] += __shfl_xor_sync(~0u, vr[j], o);
#pragma unroll
        for (int j = 0; j < 4; j++) {
            float rs = rsqrtf(vr[j] * (1.f / 64.f) + 1e-5f);
            q0[j] = fmaxf(fmaf(a0[j] * rs, gm.x, bt.x), 0.f);
            q1[j] = fmaxf(fmaf(a1[j] * rs, gm.y, bt.y), 0.f);
        }

        float bd[4];
#pragma unroll
        for (int j = 0; j < 4; j++) bd[j] = q0[j] * wb.x + q1[j] * wb.y;
#pragma unroll
        for (int o = 16; o; o >>= 1)
#pragma unroll
            for (int j = 0; j < 4; j++) bd[j] += __shfl_xor_sync(~0u, bd[j], o);
        if (lane == 0) {
#pragma unroll
            for (int j = 0; j < 4; j++)
                out[(size_t)13 * MPTS + p4 + j] = bd[j] + bb0;
        }

#pragma unroll
        for (int j = 0; j < 4; j++)
            *(float2*)&myS[j * 64 + 2 * lane] = make_float2(q0[j], q1[j]);
        __syncwarp();

        float u0[4] = {0,0,0,0}, u1[4] = {0,0,0,0};
        float v0[4] = {0,0,0,0}, v1[4] = {0,0,0,0};
#pragma unroll
        for (int i = 0; i < 64; i += 4) {
            float xj[4][4];
#pragma unroll
            for (int j = 0; j < 4; j++) {
                float4 tt = *(const float4*)&myS[j * 64 + i];
                xj[j][0] = tt.x; xj[j][1] = tt.y; xj[j][2] = tt.z; xj[j][3] = tt.w;
            }
#pragma unroll
            for (int s = 0; s < 4; s++) {
                float2 wq = *(const float2*)&sWq[(i + s) * 64 + 2 * lane];
                float2 wk = *(const float2*)&sWk[(i + s) * 64 + 2 * lane];
#pragma unroll
                for (int j = 0; j < 4; j++) {
                    u0[j] = fmaf(xj[j][s], wq.x, u0[j]);
                    u1[j] = fmaf(xj[j][s], wq.y, u1[j]);
                    v0[j] = fmaf(xj[j][s], wk.x, v0[j]);
                    v1[j] = fmaf(xj[j][s], wk.y, v1[j]);
                }
            }
        }
        __syncwarp();
#pragma unroll
        for (int j = 0; j < 4; j++) {
            size_t o = (size_t)(p4 + j) * 64 + 2 * lane;
            *(float2*)&g_Qp[o] = make_float2(u0[j], u1[j]);
            *(float2*)&g_Kb[o] = make_float2(v0[j], v1[j]);
        }
    }
}

// ---------------------------------------------------------------------------
// Kernel A2: 4 points/warp.  Vo = sem @ W_vo   (96 -> 64, single GEMV)
// ---------------------------------------------------------------------------
__global__ void __launch_bounds__(256) kA2(const float* __restrict__ sem)
{
    extern __shared__ float sm[];
    float* sW = sm;             // 6144
    float* stage = sm + 6144;   // 8 warps * 384

    for (int i = threadIdx.x; i < 6144; i += 256) sW[i] = g_Wvo[i];
    __syncthreads();

    const int lane = threadIdx.x & 31;
    float* myS = stage + (threadIdx.x >> 5) * 384;
    const int warp = (blockIdx.x * blockDim.x + threadIdx.x) >> 5;
    const int nw   = (gridDim.x * blockDim.x) >> 5;

    for (int p4 = warp * 4; p4 < MPTS; p4 += nw * 4) {
        {
            const float4* ssrc = (const float4*)(sem + (size_t)p4 * 96);
            float4* sdst = (float4*)myS;
            sdst[lane]      = ssrc[lane];
            sdst[lane + 32] = ssrc[lane + 32];
            sdst[lane + 64] = ssrc[lane + 64];
        }
        __syncwarp();

        float o0[4] = {0,0,0,0}, o1[4] = {0,0,0,0};
#pragma unroll
        for (int i = 0; i < 96; i += 4) {
            float xj[4][4];
#pragma unroll
            for (int j = 0; j < 4; j++) {
                float4 t = *(const float4*)&myS[j * 96 + i];
                xj[j][0] = t.x; xj[j][1] = t.y; xj[j][2] = t.z; xj[j][3] = t.w;
            }
#pragma unroll
            for (int s = 0; s < 4; s++) {
                float2 w = *(const float2*)&sW[(i + s) * 64 + 2 * lane];
#pragma unroll
                for (int j = 0; j < 4; j++) {
                    o0[j] = fmaf(xj[j][s], w.x, o0[j]);
                    o1[j] = fmaf(xj[j][s], w.y, o1[j]);
                }
            }
        }
        __syncwarp();
#pragma unroll
        for (int j = 0; j < 4; j++)
            *(float2*)&g_Vo[(size_t)(p4 + j) * 64 + 2 * lane] = make_float2(o0[j], o1[j]);
    }
}

// ---------------------------------------------------------------------------
// Kernel B: attention, 1 point/warp, smem-transpose logit reduction.
//   phase1: lanes compute coalesced partials for each k -> sPart[k*36+lane]
//   phase2: lane k sums its contiguous row (8x LDS.128) -> logit in lane k
// __launch_bounds__(256,4): cap regs at 64 -> 32 warps/SM (occ 50%).
// ---------------------------------------------------------------------------
__global__ void __launch_bounds__(256, 4) kB(
    const int* __restrict__ coords, const int* __restrict__ nbr,
    const float* __restrict__ pe, const float* __restrict__ bo,
    float* __restrict__ out)
{
    __shared__ float sPe[KN * 64];
    __shared__ float sBo[64];
    __shared__ float sPart[8][1024];   // per-warp 28 rows x 36 stride

    for (int i = threadIdx.x; i < KN * 64; i += 256) sPe[i] = pe[i];
    if (threadIdx.x < 64) sBo[threadIdx.x] = bo[threadIdx.x];
    __syncthreads();

    const int lane = threadIdx.x & 31;
    float* part = sPart[threadIdx.x >> 5];
    const int warp = (blockIdx.x * blockDim.x + threadIdx.x) >> 5;
    const int nw   = (gridDim.x * blockDim.x) >> 5;
    const float2 bo2 = *(const float2*)&sBo[2 * lane];

    const size_t off_aff = (size_t)14 * MPTS;
    const size_t off_ref = (size_t)41 * MPTS;
    const size_t off_nbr = (size_t)105 * MPTS;
    const size_t off_msk = (size_t)132 * MPTS;

    for (int p = warp; p < MPTS; p += nw) {
        float2 q = *(const float2*)&g_Qp[(size_t)p * 64 + 2 * lane];

        int cx = coords[3 * p], cy = coords[3 * p + 1], cz = coords[3 * p + 2];

        // pack = idx | pos<<17 | valid<<22  (idx < 2^17)
        int packed = 0;
        if (lane < KN) {
            int idx = nbr[(size_t)p * KN + lane];
            int rx = coords[3 * idx] - cx, ry = coords[3 * idx + 1] - cy,
                rz = coords[3 * idx + 2] - cz;
            int vld = (max(abs(rx), max(abs(ry), abs(rz))) <= 1);
            int pos = min(max(rx + 1, 0), 2) * 9 + min(max(ry + 1, 0), 2) * 3
                    + min(max(rz + 1, 0), 2);
            packed = idx | (pos << 17) | (vld << 22);
        }

        // phase 1: coalesced partials
#pragma unroll
        for (int k = 0; k < KN; k++) {
            int pk = __shfl_sync(~0u, packed, k);
            int idx = pk & 0x1FFFF;
            int pos = (pk >> 17) & 31;
            float2 kb = *(const float2*)&g_Kb[(size_t)idx * 64 + 2 * lane];
            float2 pr = *(const float2*)&sPe[pos * 64 + 2 * lane];
            part[k * 36 + lane] = q.x * (kb.x + pr.x) + q.y * (kb.y + pr.y);
        }
        __syncwarp();

        // phase 2: lane k sums its row
        float logit = -1e30f;
        if (lane < KN) {
            const float4* rw = (const float4*)(part + lane * 36);
            float4 t0 = rw[0], t1 = rw[1], t2 = rw[2], t3 = rw[3];
            float4 t4 = rw[4], t5 = rw[5], t6 = rw[6], t7 = rw[7];
            float s01 = (t0.x + t0.y) + (t0.z + t0.w) + (t1.x + t1.y) + (t1.z + t1.w);
            float s23 = (t2.x + t2.y) + (t2.z + t2.w) + (t3.x + t3.y) + (t3.z + t3.w);
            float s45 = (t4.x + t4.y) + (t4.z + t4.w) + (t5.x + t5.y) + (t5.z + t5.w);
            float s67 = (t6.x + t6.y) + (t6.z + t6.w) + (t7.x + t7.y) + (t7.z + t7.w);
            float s = (s01 + s23) + (s45 + s67);
            logit = (packed >> 22) ? s * 0.125f : -10000.0f;
        }
        __syncwarp();

        // softmax over warp (lanes >= 27 -> exp underflow to 0)
        float mx = logit;
#pragma unroll
        for (int o = 16; o; o >>= 1)
            mx = fmaxf(mx, __shfl_xor_sync(~0u, mx, o));
        float e = __expf(logit - mx);
        float ssum = e;
#pragma unroll
        for (int o = 16; o; o >>= 1)
            ssum += __shfl_xor_sync(~0u, ssum, o);
        float aff = e / ssum;

        // aggregate Vo (two accumulators for chain ILP)
        float2 r = *(const float2*)&g_Vo[(size_t)p * 64 + 2 * lane];
        float2 r2 = make_float2(0.f, 0.f);
#pragma unroll
        for (int k = 0; k < KN; k += 2) {
            float aa = __shfl_sync(~0u, aff, k);
            int   pk = __shfl_sync(~0u, packed, k);
            float2 v = *(const float2*)&g_Vo[(size_t)(pk & 0x1FFFF) * 64 + 2 * lane];
            r.x = fmaf(aa, v.x, r.x); r.y = fmaf(aa, v.y, r.y);
            if (k + 1 < KN) {
                float ab = __shfl_sync(~0u, aff, k + 1);
                int   pb = __shfl_sync(~0u, packed, k + 1);
                float2 w = *(const float2*)&g_Vo[(size_t)(pb & 0x1FFFF) * 64 + 2 * lane];
                r2.x = fmaf(ab, w.x, r2.x); r2.y = fmaf(ab, w.y, r2.y);
            }
        }
        r.x += r2.x; r.y += r2.y;

        *(float2*)&out[off_ref + (size_t)p * 64 + 2 * lane] =
            make_float2(r.x + bo2.x, r.y + bo2.y);
        if (lane < KN) {
            size_t a = (size_t)p * KN + lane;
            out[off_aff + a] = aff;
            out[off_nbr + a] = (float)(packed & 0x1FFFF);
            out[off_msk + a] = (packed >> 22) ? 1.f : 0.f;
        }
    }
}

// ---------------------------------------------------------------------------
// Kernel C: logits = refined_feat @ Wc + bc  (reads refined from out buffer)
// ---------------------------------------------------------------------------
__global__ void __launch_bounds__(256) kC(
    const float* __restrict__ Wc, const float* __restrict__ bc,
    float* __restrict__ out)
{
    __shared__ float sWc[832];
    __shared__ float sBc[16];
    __shared__ float stage[8 * 256];
    for (int i = threadIdx.x; i < 832; i += 256) sWc[i] = Wc[i];
    if (threadIdx.x < 16) sBc[threadIdx.x] = (threadIdx.x < 13) ? bc[threadIdx.x] : 0.f;
    __syncthreads();

    const int lane = threadIdx.x & 31;
    float* myS = stage + (threadIdx.x >> 5) * 256;
    const int warp = (blockIdx.x * blockDim.x + threadIdx.x) >> 5;
    const int nw   = (gridDim.x * blockDim.x) >> 5;
    const float* refv = out + (size_t)41 * MPTS;

    for (int p4 = warp * 4; p4 < MPTS; p4 += nw * 4) {
        {
            const float4* rs = (const float4*)(refv + (size_t)p4 * 64);
            float4* sdst = (float4*)myS;
            sdst[lane]      = rs[lane];
            sdst[lane + 32] = rs[lane + 32];
        }
        __syncwarp();

        float c[4];
#pragma unroll
        for (int j = 0; j < 4; j++) c[j] = (lane < 13) ? sBc[lane] : 0.f;
#pragma unroll
        for (int i = 0; i < 64; i += 4) {
            float xj[4][4];
#pragma unroll
            for (int j = 0; j < 4; j++) {
                float4 t = *(const float4*)&myS[j * 64 + i];
                xj[j][0] = t.x; xj[j][1] = t.y; xj[j][2] = t.z; xj[j][3] = t.w;
            }
#pragma unroll
            for (int s = 0; s < 4; s++) {
                float w = (lane < 13) ? sWc[(i + s) * 13 + lane] : 0.f;
#pragma unroll
                for (int j = 0; j < 4; j++) c[j] = fmaf(xj[j][s], w, c[j]);
            }
        }
        __syncwarp();
        if (lane < 13) {
#pragma unroll
            for (int j = 0; j < 4; j++)
                out[(size_t)(p4 + j) * 13 + lane] = c[j];
        }
    }
}

extern "C" void kernel_launch(void* const* d_in, const int* in_sizes, int n_in,
                              void* d_out, int out_size)
{
    const float* geo    = (const float*)d_in[0];
    const float* sem    = (const float*)d_in[1];
    const int*   coords = (const int*)d_in[2];
    const int*   nbr    = (const int*)d_in[3];   // int32 (JAX x64 off)
    const float* Wg     = (const float*)d_in[4];
    const float* gam    = (const float*)d_in[5];
    const float* bet    = (const float*)d_in[6];
    const float* Wb     = (const float*)d_in[7];
    const float* bb     = (const float*)d_in[8];
    const float* Wq     = (const float*)d_in[9];
    const float* Wk     = (const float*)d_in[10];
    const float* Wv     = (const float*)d_in[11];
    const float* pe     = (const float*)d_in[12];
    const float* Wo     = (const float*)d_in[13];
    const float* bo     = (const float*)d_in[14];
    const float* Wc     = (const float*)d_in[15];
    const float* bc     = (const float*)d_in[16];
    float* out = (float*)d_out;

    const int smemA1 = 14528 * 4;   // 58112 B
    const int smemA2 = 9216 * 4;    // 36864 B
    cudaFuncSetAttribute(kA1, cudaFuncAttributeMaxDynamicSharedMemorySize, smemA1);

    kW<<<24, 256>>>(Wv, Wo);
    kA1<<<592, 256, smemA1>>>(geo, Wg, gam, bet, Wb, bb, Wq, Wk, out);
    kA2<<<592, 256, smemA2>>>(sem);
    kB<<<12500, 256>>>(coords, nbr, pe, bo, out);
    kC<<<592, 256>>>(Wc, bc, out);
}